// round 15
// baseline (speedup 1.0000x reference)
#include <cuda_runtime.h>
#include <cuda_fp16.h>
#include <cstdint>
#include <math.h>

// Problem constants (fixed by the reference setup_inputs)
#define T_TOK   1024
#define H_DIM   1024
#define I_DIM   2816
#define E_NUM   8
#define S_NUM   (T_TOK * 2)      // 2048 (token, expert) slots
#define S_PAD   (S_NUM + 128)    // +128 rows: unconditional tile loads
#define MAX_TILES 24
#define NBLK1   (I_DIM / 64)     // 44 n-blocks in gemm1

// GEMM tiling
#define BK  64
#define LDA 72                   // 64 + 8 halfs pad: 144B row stride -> conflict-free LDSM

// dynamic smem sizes (halfs)
#define G1_A_HALFS   (2 * 128 * LDA)
#define G1_B_HALFS   (2 * 64 * LDA)
#define G1_SMEM_B    ((G1_A_HALFS + 2 * G1_B_HALFS) * 2)     // 73728 bytes
#define G2_SMEM_B    ((G1_A_HALFS + G1_B_HALFS) * 2)         // 55296 bytes

// ---------------- device scratch (static, allocation-free) ----------------
__device__ int   d_slot_token[S_NUM];
__device__ float d_slot_gate[S_NUM];
__device__ int   d_tile_e[MAX_TILES];
__device__ int   d_tile_r0[MAX_TILES];
__device__ int   d_tile_r1[MAX_TILES];
__device__ int   d_num_tiles;
__device__ __align__(16) __half d_xg [(size_t)S_PAD * H_DIM];   // gathered X, fp16
__device__ __align__(16) __half d_act[(size_t)S_PAD * I_DIM];   // 12.3 MB fp16

// ---------------- helpers ----------------
__device__ __forceinline__ uint32_t smem_u32(const void* p) {
    return (uint32_t)__cvta_generic_to_shared(p);
}

#define CP_ASYNC_16(dst_u32, src_ptr) \
    asm volatile("cp.async.cg.shared.global [%0], [%1], 16;" \
                 :: "r"(dst_u32), "l"(src_ptr))
#define CP_ASYNC_COMMIT() asm volatile("cp.async.commit_group;" ::: "memory")
#define CP_ASYNC_WAIT0()  asm volatile("cp.async.wait_group 0;" ::: "memory")

__device__ __forceinline__ void ldsm_x4(uint32_t* r, uint32_t addr) {
    asm volatile("ldmatrix.sync.aligned.m8n8.x4.shared.b16 {%0,%1,%2,%3}, [%4];"
                 : "=r"(r[0]), "=r"(r[1]), "=r"(r[2]), "=r"(r[3]) : "r"(addr));
}

__device__ __forceinline__ void mma_f16(float c[4], const uint32_t a[4], uint32_t b0, uint32_t b1) {
    asm volatile(
        "mma.sync.aligned.m16n8k16.row.col.f32.f16.f16.f32 "
        "{%0,%1,%2,%3}, {%4,%5,%6,%7}, {%8,%9}, {%0,%1,%2,%3};\n"
        : "+f"(c[0]), "+f"(c[1]), "+f"(c[2]), "+f"(c[3])
        : "r"(a[0]), "r"(a[1]), "r"(a[2]), "r"(a[3]), "r"(b0), "r"(b1));
}

__device__ __forceinline__ uint32_t pack2(float x, float y) {
    __half2 h = __floats2half2_rn(x, y);
    return *reinterpret_cast<uint32_t*>(&h);
}

// load float4 and convert immediately to 4 halfs (uint2) — halves staging regs
__device__ __forceinline__ uint2 ldg_cvt4(const float* p) {
    float4 v = *(const float4*)p;
    uint2 u;
    u.x = pack2(v.x, v.y);
    u.y = pack2(v.z, v.w);
    return u;
}

// ---------------- zero output ----------------
__global__ void zero_kernel(float* __restrict__ out) {
    out[blockIdx.x * blockDim.x + threadIdx.x] = 0.0f;
}

// ---------------- router: top-2 softmax gates + expert-grouped slots ----------------
__global__ void router_kernel(const float* __restrict__ logits) {
    __shared__ int s_cnt[E_NUM];
    __shared__ int s_off[E_NUM + 1];
    __shared__ int s_cur[E_NUM];

    int t = threadIdx.x;            // one token per thread, blockDim == T_TOK
    if (t < E_NUM) s_cnt[t] = 0;
    __syncthreads();

    float l[E_NUM];
#pragma unroll
    for (int e = 0; e < E_NUM; e++) l[e] = logits[t * E_NUM + e];

    int e0 = 0;
#pragma unroll
    for (int e = 1; e < E_NUM; e++) if (l[e] > l[e0]) e0 = e;
    int e1 = (e0 == 0) ? 1 : 0;
#pragma unroll
    for (int e = 0; e < E_NUM; e++) if (e != e0 && l[e] > l[e1]) e1 = e;

    // renormalized top-2 softmax == softmax over {l0, l1}
    float d  = expf(l[e1] - l[e0]);       // <= 1
    float g0 = 1.0f / (1.0f + d);
    float g1 = 1.0f - g0;

    atomicAdd(&s_cnt[e0], 1);
    atomicAdd(&s_cnt[e1], 1);
    __syncthreads();

    if (t == 0) {
        int acc = 0;
        for (int e = 0; e < E_NUM; e++) { s_off[e] = acc; s_cur[e] = acc; acc += s_cnt[e]; }
        s_off[E_NUM] = acc;   // == S_NUM
    }
    __syncthreads();

    int p0 = atomicAdd(&s_cur[e0], 1);
    d_slot_token[p0] = t; d_slot_gate[p0] = g0;
    int p1 = atomicAdd(&s_cur[e1], 1);
    d_slot_token[p1] = t; d_slot_gate[p1] = g1;

    if (t == 0) {
        int nt = 0;
        for (int e = 0; e < E_NUM; e++) {
            for (int r = s_off[e]; r < s_off[e + 1]; r += 128) {
                d_tile_e[nt]  = e;
                d_tile_r0[nt] = r;
                d_tile_r1[nt] = min(r + 128, s_off[e + 1]);
                nt++;
            }
        }
        d_num_tiles = nt;
    }
}

// ---------------- gather: d_xg[slot] = fp16(X[token(slot)]) ----------------
__global__ void gather_kernel(const float* __restrict__ X) {
    int idx  = blockIdx.x * blockDim.x + threadIdx.x;
    int slot = idx >> 7;                 // H/8 = 128 chunks per row
    int c    = (idx & 127) * 8;
    int tok  = d_slot_token[slot];
    const float* src = X + (size_t)tok * H_DIM + c;
    float4 v0 = *(const float4*)(src);
    float4 v1 = *(const float4*)(src + 4);
    uint4 u;
    u.x = pack2(v0.x, v0.y); u.y = pack2(v0.z, v0.w);
    u.z = pack2(v1.x, v1.y); u.w = pack2(v1.z, v1.w);
    *(uint4*)(d_xg + (size_t)slot * H_DIM + c) = u;
}

// ---------------- GEMM1: act = silu(Xg@W1^T) * (Xg@W3^T), fp16 MMA ----------------
// PERSISTENT: grid = 296 CTAs grid-striding over (tile, n0) work items.
// block tile 128(M) x 64(N) per B-matrix; 8 warps 4m x 2n (warp 32x32 per matrix)
// BK=64, 2-stage smem ping-pong (dynamic smem). cp.async A; B LDG+cvt-on-load.
__global__ __launch_bounds__(256, 2)
void gemm1_kernel(const float* __restrict__ W1,
                  const float* __restrict__ W3) {
    extern __shared__ __half smem[];
    __half* sA  = smem;                         // [2][128*LDA]
    __half* sB1 = smem + G1_A_HALFS;            // [2][64*LDA]
    __half* sB3 = sB1 + G1_B_HALFS;             // [2][64*LDA]

    const int tid  = threadIdx.x;
    const int warp = tid >> 5, lane = tid & 31;
    const int g = lane >> 2, tg = lane & 3;
    const int wm = warp & 3, wn = warp >> 2;     // warp tile (wm*32, wn*32)
    const int q = lane >> 3, j = lane & 7;       // ldmatrix lane decomposition

    // A cp.async geometry: 1 row/thread (tid>>1), 4 x 16B chunks over 32 halfs
    const int arow_ld = tid >> 1;                // 0..127
    const int acol_ld = (tid & 1) * 32;          // 0 or 32 halfs
    // B load geometry: row tid>>2 (0..63), 16 fp32 at (tid&3)*16
    const int brow_ld = tid >> 2;
    const int bcol_ld = (tid & 3) * 16;

    const int n_items = d_num_tiles * NBLK1;

    for (int item = blockIdx.x; item < n_items; item += gridDim.x) {
        const int tile = item / NBLK1;
        const int nblk = item - tile * NBLK1;
        const int e    = d_tile_e[tile];
        const int r0   = d_tile_r0[tile];
        const int rows = d_tile_r1[tile] - r0;
        const int n0   = nblk * 64;

        const __half* Ag  = d_xg + (size_t)r0 * H_DIM + (size_t)arow_ld * H_DIM;
        const float*  W1e = W1 + (size_t)e * I_DIM * H_DIM + (size_t)(n0 + brow_ld) * H_DIM;
        const float*  W3e = W3 + (size_t)e * I_DIM * H_DIM + (size_t)(n0 + brow_ld) * H_DIM;

        uint2 rB1[4], rB3[4];

        // ---- stage 0 ----
#pragma unroll
        for (int c = 0; c < 4; c++)
            CP_ASYNC_16(smem_u32(&sA[arow_ld * LDA + acol_ld + c * 8]), Ag + acol_ld + c * 8);
        CP_ASYNC_COMMIT();
#pragma unroll
        for (int i = 0; i < 4; i++) {
            rB1[i] = ldg_cvt4(W1e + bcol_ld + 4 * i);
            rB3[i] = ldg_cvt4(W3e + bcol_ld + 4 * i);
        }
#pragma unroll
        for (int i = 0; i < 4; i++) {
            *(uint2*)&sB1[brow_ld * LDA + bcol_ld + 4 * i] = rB1[i];
            *(uint2*)&sB3[brow_ld * LDA + bcol_ld + 4 * i] = rB3[i];
        }
        CP_ASYNC_WAIT0();
        __syncthreads();

        float acc1[2][4][4], acc3[2][4][4];
#pragma unroll
        for (int a = 0; a < 2; a++)
#pragma unroll
            for (int b = 0; b < 4; b++)
#pragma unroll
                for (int c = 0; c < 4; c++) { acc1[a][b][c] = 0.f; acc3[a][b][c] = 0.f; }

        const int NT = H_DIM / BK;       // 16 K-tiles (even: last reads buf 1)
        for (int t = 0; t < NT; t++) {
            const int cur = t & 1;
            const bool more = (t + 1 < NT);
            __half* cA  = sA  + cur * (128 * LDA);
            __half* cB1 = sB1 + cur * (64 * LDA);
            __half* cB3 = sB3 + cur * (64 * LDA);

            // issue next-tile async A copies + B LDGs (convert on load)
            if (more) {
                const int kn = (t + 1) * BK;
                __half* nA = sA + (cur ^ 1) * (128 * LDA);
#pragma unroll
                for (int c = 0; c < 4; c++)
                    CP_ASYNC_16(smem_u32(&nA[arow_ld * LDA + acol_ld + c * 8]),
                                Ag + kn + acol_ld + c * 8);
                CP_ASYNC_COMMIT();
#pragma unroll
                for (int i = 0; i < 4; i++) {
                    rB1[i] = ldg_cvt4(W1e + kn + bcol_ld + 4 * i);
                    rB3[i] = ldg_cvt4(W3e + kn + bcol_ld + 4 * i);
                }
            }

            // compute K-tile from buf[cur]: 4 ksteps of m16n8k16
#pragma unroll
            for (int ks = 0; ks < BK; ks += 16) {
                uint32_t af[2][4];
#pragma unroll
                for (int mt = 0; mt < 2; mt++) {
                    int arow = wm * 32 + mt * 16 + j + (q & 1) * 8;
                    int acol = ks + (q >> 1) * 8;
                    ldsm_x4(af[mt], smem_u32(&cA[arow * LDA + acol]));
                }
                uint32_t bf1[2][4], bf3[2][4];
#pragma unroll
                for (int pr = 0; pr < 2; pr++) {
                    int brow = wn * 32 + pr * 16 + j + (q >> 1) * 8;
                    int bcol = ks + (q & 1) * 8;
                    ldsm_x4(bf1[pr], smem_u32(&cB1[brow * LDA + bcol]));
                    ldsm_x4(bf3[pr], smem_u32(&cB3[brow * LDA + bcol]));
                }
#pragma unroll
                for (int mt = 0; mt < 2; mt++)
#pragma unroll
                    for (int nt = 0; nt < 4; nt++) {
                        int pr = nt >> 1, o = (nt & 1) * 2;
                        mma_f16(acc1[mt][nt], af[mt], bf1[pr][o], bf1[pr][o + 1]);
                        mma_f16(acc3[mt][nt], af[mt], bf3[pr][o], bf3[pr][o + 1]);
                    }
            }

            if (more) {
                __half* nB1 = sB1 + (cur ^ 1) * (64 * LDA);
                __half* nB3 = sB3 + (cur ^ 1) * (64 * LDA);
#pragma unroll
                for (int i = 0; i < 4; i++) {
                    *(uint2*)&nB1[brow_ld * LDA + bcol_ld + 4 * i] = rB1[i];
                    *(uint2*)&nB3[brow_ld * LDA + bcol_ld + 4 * i] = rB3[i];
                }
                CP_ASYNC_WAIT0();
                __syncthreads();
            }
        }

        // epilogue: act = silu(h1) * h3, stored fp16 as half2.
        // (next item's stage 0 targets buf 0; final K-tile above read buf 1)
#pragma unroll
        for (int mt = 0; mt < 2; mt++) {
#pragma unroll
            for (int nt = 0; nt < 4; nt++) {
#pragma unroll
                for (int p = 0; p < 2; p++) {
                    int m = wm * 32 + mt * 16 + g + p * 8;
                    if (m < rows) {
                        float h1a = acc1[mt][nt][2 * p],     h3a = acc3[mt][nt][2 * p];
                        float h1b = acc1[mt][nt][2 * p + 1], h3b = acc3[mt][nt][2 * p + 1];
                        float va = (h1a / (1.0f + __expf(-h1a))) * h3a;
                        float vb = (h1b / (1.0f + __expf(-h1b))) * h3b;
                        int n = n0 + wn * 32 + nt * 8 + tg * 2;
                        *(__half2*)&d_act[(size_t)(r0 + m) * I_DIM + n] =
                            __floats2half2_rn(va, vb);
                    }
                }
            }
        }
    }
}

// ---------------- GEMM2: out += gate * (act @ W2^T), fp16 MMA ----------------
// block tile 128(M) x 64(N); 8 warps 4m x 2n (warp 32x32); BK=64; cp.async A
// grid: (H_DIM/64 = 16, MAX_TILES), block: 256
__global__ __launch_bounds__(256, 2)
void gemm2_kernel(const float* __restrict__ W2, float* __restrict__ out) {
    int tile = blockIdx.y;
    if (tile >= d_num_tiles) return;
    const int e    = d_tile_e[tile];
    const int r0   = d_tile_r0[tile];
    const int rows = d_tile_r1[tile] - r0;
    const int n0   = blockIdx.x * 64;

    extern __shared__ __half smem[];
    __half* sA = smem;                          // [2][128*LDA]
    __half* sB = smem + G1_A_HALFS;             // [2][64*LDA]

    const int tid  = threadIdx.x;
    const int warp = tid >> 5, lane = tid & 31;
    const int g = lane >> 2, tg = lane & 3;
    const int wm = warp & 3, wn = warp >> 2;     // warp tile (wm*32, wn*32)
    const int q = lane >> 3, j = lane & 7;

    const int arow_ld = tid >> 1;                // 0..127
    const int acol_ld = (tid & 1) * 32;
    const int brow_ld = tid >> 2;                // 0..63
    const int bcol_ld = (tid & 3) * 16;

    const __half* Ap  = d_act + (size_t)(r0 + arow_ld) * I_DIM;  // padded -> unconditional
    const float*  W2e = W2 + (size_t)e * H_DIM * I_DIM + (size_t)(n0 + brow_ld) * I_DIM;

    uint2 rB[4];

    // ---- stage 0 ----
#pragma unroll
    for (int c = 0; c < 4; c++)
        CP_ASYNC_16(smem_u32(&sA[arow_ld * LDA + acol_ld + c * 8]), Ap + acol_ld + c * 8);
    CP_ASYNC_COMMIT();
#pragma unroll
    for (int i = 0; i < 4; i++)
        rB[i] = ldg_cvt4(W2e + bcol_ld + 4 * i);
#pragma unroll
    for (int i = 0; i < 4; i++)
        *(uint2*)&sB[brow_ld * LDA + bcol_ld + 4 * i] = rB[i];
    CP_ASYNC_WAIT0();
    __syncthreads();

    float acc[2][4][4];
#pragma unroll
    for (int a = 0; a < 2; a++)
#pragma unroll
        for (int b = 0; b < 4; b++)
#pragma unroll
            for (int c = 0; c < 4; c++) acc[a][b][c] = 0.f;

    const int NT = I_DIM / BK;       // 44 K-tiles
    for (int t = 0; t < NT; t++) {
        const int cur = t & 1;
        const bool more = (t + 1 < NT);
        __half* cA = sA + cur * (128 * LDA);
        __half* cB = sB + cur * (64 * LDA);

        if (more) {
            const int kn = (t + 1) * BK;
            __half* nA = sA + (cur ^ 1) * (128 * LDA);
#pragma unroll
            for (int c = 0; c < 4; c++)
                CP_ASYNC_16(smem_u32(&nA[arow_ld * LDA + acol_ld + c * 8]),
                            Ap + kn + acol_ld + c * 8);
            CP_ASYNC_COMMIT();
#pragma unroll
            for (int i = 0; i < 4; i++)
                rB[i] = ldg_cvt4(W2e + kn + bcol_ld + 4 * i);
        }

#pragma unroll
        for (int ks = 0; ks < BK; ks += 16) {
            uint32_t af[2][4];
#pragma unroll
            for (int mt = 0; mt < 2; mt++) {
                int arow = wm * 32 + mt * 16 + j + (q & 1) * 8;
                int acol = ks + (q >> 1) * 8;
                ldsm_x4(af[mt], smem_u32(&cA[arow * LDA + acol]));
            }
            uint32_t bf[2][4];
#pragma unroll
            for (int pr = 0; pr < 2; pr++) {
                int brow = wn * 32 + pr * 16 + j + (q >> 1) * 8;
                int bcol = ks + (q & 1) * 8;
                ldsm_x4(bf[pr], smem_u32(&cB[brow * LDA + bcol]));
            }
#pragma unroll
            for (int mt = 0; mt < 2; mt++)
#pragma unroll
                for (int nt = 0; nt < 4; nt++) {
                    int pr = nt >> 1, o = (nt & 1) * 2;
                    mma_f16(acc[mt][nt], af[mt], bf[pr][o], bf[pr][o + 1]);
                }
        }

        if (more) {
            __half* nB = sB + (cur ^ 1) * (64 * LDA);
#pragma unroll
            for (int i = 0; i < 4; i++)
                *(uint2*)&nB[brow_ld * LDA + bcol_ld + 4 * i] = rB[i];
            CP_ASYNC_WAIT0();
            __syncthreads();
        }
    }

    // epilogue: weighted scatter-add (exactly 2 contributions per (token, h);
    // fp32 add is commutative -> bitwise deterministic)
    int   tok_h[2][2];
    float gat_h[2][2];
#pragma unroll
    for (int mt = 0; mt < 2; mt++)
#pragma unroll
        for (int hh = 0; hh < 2; hh++) {
            int m = wm * 32 + mt * 16 + g + hh * 8;
            if (m < rows) {
                tok_h[mt][hh] = d_slot_token[r0 + m];
                gat_h[mt][hh] = d_slot_gate[r0 + m];
            } else {
                tok_h[mt][hh] = -1;
                gat_h[mt][hh] = 0.f;
            }
        }

#pragma unroll
    for (int mt = 0; mt < 2; mt++) {
#pragma unroll
        for (int nt = 0; nt < 4; nt++) {
#pragma unroll
            for (int i = 0; i < 4; i++) {
                int hh = (i >= 2) ? 1 : 0;
                int tok = tok_h[mt][hh];
                if (tok >= 0) {
                    int n = n0 + wn * 32 + nt * 8 + tg * 2 + (i & 1);
                    atomicAdd(&out[(size_t)tok * H_DIM + n],
                              gat_h[mt][hh] * acc[mt][nt][i]);
                }
            }
        }
    }
}

// ---------------- launch ----------------
extern "C" void kernel_launch(void* const* d_in, const int* in_sizes, int n_in,
                              void* d_out, int out_size) {
    const float* hs     = (const float*)d_in[0];   // [T, H]
    const float* logits = (const float*)d_in[1];   // [T, E]
    const float* w1     = (const float*)d_in[2];   // [E, I, H]
    const float* w3     = (const float*)d_in[3];   // [E, I, H]
    const float* w2     = (const float*)d_in[4];   // [E, H, I]
    float* out = (float*)d_out;                    // [T, H]

    // idempotent attribute sets (host-side, not captured as graph nodes)
    cudaFuncSetAttribute(gemm1_kernel, cudaFuncAttributeMaxDynamicSharedMemorySize, G1_SMEM_B);
    cudaFuncSetAttribute(gemm2_kernel, cudaFuncAttributeMaxDynamicSharedMemorySize, G2_SMEM_B);

    zero_kernel<<<(T_TOK * H_DIM) / 256, 256>>>(out);
    router_kernel<<<1, T_TOK>>>(logits);
    gather_kernel<<<(S_NUM * H_DIM / 8) / 256, 256>>>(hs);
    gemm1_kernel<<<296, 256, G1_SMEM_B>>>(w1, w3);             // persistent
    gemm2_kernel<<<dim3(H_DIM / 64, MAX_TILES), 256, G2_SMEM_B>>>(w2, out);
}

// round 16
// speedup vs baseline: 1.2158x; 1.2158x over previous
#include <cuda_runtime.h>
#include <cuda_fp16.h>
#include <cstdint>
#include <math.h>

// Problem constants (fixed by the reference setup_inputs)
#define T_TOK   1024
#define H_DIM   1024
#define I_DIM   2816
#define E_NUM   8
#define S_NUM   (T_TOK * 2)      // 2048 (token, expert) slots
#define S_PAD   (S_NUM + 128)    // +128 rows: unconditional tile loads
#define MAX_TILES 24

// GEMM tiling
#define BK 32
#define LDA 40                   // 32 + 8 halfs pad: 80B row stride -> conflict-free LDSM

// ---------------- device scratch (static, allocation-free) ----------------
__device__ int   d_slot_token[S_NUM];
__device__ float d_slot_gate[S_NUM];
__device__ int   d_tok_slot[T_TOK * 2];          // token -> its 2 slots
__device__ int   d_tile_e[MAX_TILES];
__device__ int   d_tile_r0[MAX_TILES];
__device__ int   d_tile_r1[MAX_TILES];
__device__ int   d_num_tiles;
__device__ __align__(16) __half d_xg [(size_t)S_PAD * H_DIM];   // gathered X, fp16
__device__ __align__(16) __half d_act[(size_t)S_PAD * I_DIM];   // 12.3 MB fp16
__device__ __align__(16) float  d_y  [(size_t)S_NUM * H_DIM];   // 8 MB gated partials

// ---------------- helpers ----------------
__device__ __forceinline__ uint32_t smem_u32(const void* p) {
    return (uint32_t)__cvta_generic_to_shared(p);
}

#define CP_ASYNC_16(dst_u32, src_ptr) \
    asm volatile("cp.async.cg.shared.global [%0], [%1], 16;" \
                 :: "r"(dst_u32), "l"(src_ptr))
#define CP_ASYNC_COMMIT() asm volatile("cp.async.commit_group;" ::: "memory")
#define CP_ASYNC_WAIT0()  asm volatile("cp.async.wait_group 0;" ::: "memory")

__device__ __forceinline__ void ldsm_x4(uint32_t* r, uint32_t addr) {
    asm volatile("ldmatrix.sync.aligned.m8n8.x4.shared.b16 {%0,%1,%2,%3}, [%4];"
                 : "=r"(r[0]), "=r"(r[1]), "=r"(r[2]), "=r"(r[3]) : "r"(addr));
}

__device__ __forceinline__ void mma_f16(float c[4], const uint32_t a[4], uint32_t b0, uint32_t b1) {
    asm volatile(
        "mma.sync.aligned.m16n8k16.row.col.f32.f16.f16.f32 "
        "{%0,%1,%2,%3}, {%4,%5,%6,%7}, {%8,%9}, {%0,%1,%2,%3};\n"
        : "+f"(c[0]), "+f"(c[1]), "+f"(c[2]), "+f"(c[3])
        : "r"(a[0]), "r"(a[1]), "r"(a[2]), "r"(a[3]), "r"(b0), "r"(b1));
}

__device__ __forceinline__ uint32_t pack2(float x, float y) {
    __half2 h = __floats2half2_rn(x, y);
    return *reinterpret_cast<uint32_t*>(&h);
}

// ---------------- router: top-2 softmax gates + expert-grouped slots ----------------
__global__ void router_kernel(const float* __restrict__ logits) {
    __shared__ int s_cnt[E_NUM];
    __shared__ int s_off[E_NUM + 1];
    __shared__ int s_cur[E_NUM];

    int t = threadIdx.x;            // one token per thread, blockDim == T_TOK
    if (t < E_NUM) s_cnt[t] = 0;
    __syncthreads();

    float l[E_NUM];
#pragma unroll
    for (int e = 0; e < E_NUM; e++) l[e] = logits[t * E_NUM + e];

    int e0 = 0;
#pragma unroll
    for (int e = 1; e < E_NUM; e++) if (l[e] > l[e0]) e0 = e;
    int e1 = (e0 == 0) ? 1 : 0;
#pragma unroll
    for (int e = 0; e < E_NUM; e++) if (e != e0 && l[e] > l[e1]) e1 = e;

    // renormalized top-2 softmax == softmax over {l0, l1}
    float d  = expf(l[e1] - l[e0]);       // <= 1
    float g0 = 1.0f / (1.0f + d);
    float g1 = 1.0f - g0;

    atomicAdd(&s_cnt[e0], 1);
    atomicAdd(&s_cnt[e1], 1);
    __syncthreads();

    if (t == 0) {
        int acc = 0;
        for (int e = 0; e < E_NUM; e++) { s_off[e] = acc; s_cur[e] = acc; acc += s_cnt[e]; }
        s_off[E_NUM] = acc;   // == S_NUM
    }
    __syncthreads();

    int p0 = atomicAdd(&s_cur[e0], 1);
    d_slot_token[p0] = t; d_slot_gate[p0] = g0;
    int p1 = atomicAdd(&s_cur[e1], 1);
    d_slot_token[p1] = t; d_slot_gate[p1] = g1;
    d_tok_slot[t * 2]     = p0;
    d_tok_slot[t * 2 + 1] = p1;

    if (t == 0) {
        int nt = 0;
        for (int e = 0; e < E_NUM; e++) {
            for (int r = s_off[e]; r < s_off[e + 1]; r += 128) {
                d_tile_e[nt]  = e;
                d_tile_r0[nt] = r;
                d_tile_r1[nt] = min(r + 128, s_off[e + 1]);
                nt++;
            }
        }
        d_num_tiles = nt;
    }
}

// ---------------- gather: d_xg[slot] = fp16(X[token(slot)]) ----------------
__global__ void gather_kernel(const float* __restrict__ X) {
    int idx  = blockIdx.x * blockDim.x + threadIdx.x;
    int slot = idx >> 7;                 // H/8 = 128 chunks per row
    int c    = (idx & 127) * 8;
    int tok  = d_slot_token[slot];
    const float* src = X + (size_t)tok * H_DIM + c;
    float4 v0 = *(const float4*)(src);
    float4 v1 = *(const float4*)(src + 4);
    uint4 u;
    u.x = pack2(v0.x, v0.y); u.y = pack2(v0.z, v0.w);
    u.z = pack2(v1.x, v1.y); u.w = pack2(v1.z, v1.w);
    *(uint4*)(d_xg + (size_t)slot * H_DIM + c) = u;
}

// ---------------- combine: out[t] = y[slot0(t)] + y[slot1(t)] ----------------
// grid: T*H/4/256 blocks, 256 threads; float4 per thread
__global__ void combine_kernel(float* __restrict__ out) {
    int idx = blockIdx.x * blockDim.x + threadIdx.x;
    int t   = idx >> 8;                  // H/4 = 256 chunks per token
    int c   = (idx & 255) * 4;
    int s0  = d_tok_slot[t * 2];
    int s1  = d_tok_slot[t * 2 + 1];
    float4 a = *(const float4*)(d_y + (size_t)s0 * H_DIM + c);
    float4 b = *(const float4*)(d_y + (size_t)s1 * H_DIM + c);
    float4 r;
    r.x = a.x + b.x; r.y = a.y + b.y; r.z = a.z + b.z; r.w = a.w + b.w;
    *(float4*)(out + (size_t)t * H_DIM + c) = r;
}

// ---------------- GEMM1: act = silu(Xg@W1^T) * (Xg@W3^T), fp16 MMA ----------------
// block tile 128(M) x 64(N) per B-matrix; 8 warps 4m x 2n (warp 32x32 per matrix)
// A tile via cp.async; B via LDG (raw fp32 staging, convert AFTER compute).
// 2-stage smem ping-pong, 1 barrier per K-tile. 2 CTAs/SM.
// grid: (I_DIM/64 = 44, MAX_TILES), block: 256
__global__ __launch_bounds__(256, 2)
void gemm1_kernel(const float* __restrict__ W1,
                  const float* __restrict__ W3) {
    int tile = blockIdx.y;
    if (tile >= d_num_tiles) return;
    const int e    = d_tile_e[tile];
    const int r0   = d_tile_r0[tile];
    const int rows = d_tile_r1[tile] - r0;
    const int n0   = blockIdx.x * 64;

    __shared__ __half sA [2][128 * LDA];
    __shared__ __half sB1[2][64 * LDA];
    __shared__ __half sB3[2][64 * LDA];

    const int tid  = threadIdx.x;
    const int warp = tid >> 5, lane = tid & 31;
    const int g = lane >> 2, tg = lane & 3;
    const int wm = warp & 3, wn = warp >> 2;     // warp tile (wm*32, wn*32)
    const int lrow = tid >> 3;                   // 0..31 (B rows, 2 iters)
    const int lk   = (tid & 7) * 4;              // 0..28 step 4 (B cols fp32)
    const int q = lane >> 3, j = lane & 7;       // ldmatrix lane decomposition

    // A cp.async geometry: 2 rows/thread, 8 halfs (16B) per row chunk
    const int ar = tid >> 2;                     // 0..63 (+64 for second row)
    const int ac = (tid & 3) * 8;                // 0,8,16,24 halfs

    const __half* Ag  = d_xg + (size_t)r0 * H_DIM;
    const float*  W1e = W1 + (size_t)e * I_DIM * H_DIM;
    const float*  W3e = W3 + (size_t)e * I_DIM * H_DIM;

    float4 rB1[2], rB3[2];

    // ---- stage 0 ----
#pragma unroll
    for (int i = 0; i < 2; i++) {
        int row = ar + 64 * i;
        CP_ASYNC_16(smem_u32(&sA[0][row * LDA + ac]), Ag + (size_t)row * H_DIM + ac);
    }
    CP_ASYNC_COMMIT();
#pragma unroll
    for (int i = 0; i < 2; i++) {
        rB1[i] = *(const float4*)(W1e + (size_t)(n0 + lrow + 32 * i) * H_DIM + lk);
        rB3[i] = *(const float4*)(W3e + (size_t)(n0 + lrow + 32 * i) * H_DIM + lk);
    }
#pragma unroll
    for (int i = 0; i < 2; i++) {
        uint2 u1, u3;
        u1.x = pack2(rB1[i].x, rB1[i].y); u1.y = pack2(rB1[i].z, rB1[i].w);
        u3.x = pack2(rB3[i].x, rB3[i].y); u3.y = pack2(rB3[i].z, rB3[i].w);
        *(uint2*)&sB1[0][(lrow + 32 * i) * LDA + lk] = u1;
        *(uint2*)&sB3[0][(lrow + 32 * i) * LDA + lk] = u3;
    }
    CP_ASYNC_WAIT0();
    __syncthreads();

    float acc1[2][4][4], acc3[2][4][4];
#pragma unroll
    for (int a = 0; a < 2; a++)
#pragma unroll
        for (int b = 0; b < 4; b++)
#pragma unroll
            for (int c = 0; c < 4; c++) { acc1[a][b][c] = 0.f; acc3[a][b][c] = 0.f; }

    const int NT = H_DIM / BK;       // 32 K-tiles
    for (int t = 0; t < NT; t++) {
        const int cur = t & 1;
        const bool more = (t + 1 < NT);

        // issue next-tile async A copies + B LDGs before compute
        if (more) {
            const int kn = (t + 1) * BK;
            const int nxt = cur ^ 1;
#pragma unroll
            for (int i = 0; i < 2; i++) {
                int row = ar + 64 * i;
                CP_ASYNC_16(smem_u32(&sA[nxt][row * LDA + ac]),
                            Ag + (size_t)row * H_DIM + kn + ac);
            }
            CP_ASYNC_COMMIT();
#pragma unroll
            for (int i = 0; i < 2; i++) {
                rB1[i] = *(const float4*)(W1e + (size_t)(n0 + lrow + 32 * i) * H_DIM + kn + lk);
                rB3[i] = *(const float4*)(W3e + (size_t)(n0 + lrow + 32 * i) * H_DIM + kn + lk);
            }
        }

        // compute K-tile from buf[cur]
#pragma unroll
        for (int ks = 0; ks < BK; ks += 16) {
            uint32_t af[2][4];
#pragma unroll
            for (int mt = 0; mt < 2; mt++) {
                int arow = wm * 32 + mt * 16 + j + (q & 1) * 8;
                int acol = ks + (q >> 1) * 8;
                ldsm_x4(af[mt], smem_u32(&sA[cur][arow * LDA + acol]));
            }
            uint32_t bf1[2][4], bf3[2][4];
#pragma unroll
            for (int pr = 0; pr < 2; pr++) {
                int brow = wn * 32 + pr * 16 + j + (q >> 1) * 8;
                int bcol = ks + (q & 1) * 8;
                ldsm_x4(bf1[pr], smem_u32(&sB1[cur][brow * LDA + bcol]));
                ldsm_x4(bf3[pr], smem_u32(&sB3[cur][brow * LDA + bcol]));
            }
#pragma unroll
            for (int mt = 0; mt < 2; mt++)
#pragma unroll
                for (int nt = 0; nt < 4; nt++) {
                    int pr = nt >> 1, o = (nt & 1) * 2;
                    mma_f16(acc1[mt][nt], af[mt], bf1[pr][o], bf1[pr][o + 1]);
                    mma_f16(acc3[mt][nt], af[mt], bf3[pr][o], bf3[pr][o + 1]);
                }
        }

        if (more) {
            const int nxt = cur ^ 1;
#pragma unroll
            for (int i = 0; i < 2; i++) {
                uint2 u1, u3;
                u1.x = pack2(rB1[i].x, rB1[i].y); u1.y = pack2(rB1[i].z, rB1[i].w);
                u3.x = pack2(rB3[i].x, rB3[i].y); u3.y = pack2(rB3[i].z, rB3[i].w);
                *(uint2*)&sB1[nxt][(lrow + 32 * i) * LDA + lk] = u1;
                *(uint2*)&sB3[nxt][(lrow + 32 * i) * LDA + lk] = u3;
            }
            CP_ASYNC_WAIT0();
            __syncthreads();
        }
    }

    // epilogue: act = silu(h1) * h3, stored fp16 as half2
#pragma unroll
    for (int mt = 0; mt < 2; mt++) {
#pragma unroll
        for (int nt = 0; nt < 4; nt++) {
#pragma unroll
            for (int p = 0; p < 2; p++) {
                int m = wm * 32 + mt * 16 + g + p * 8;
                if (m < rows) {
                    float h1a = acc1[mt][nt][2 * p],     h3a = acc3[mt][nt][2 * p];
                    float h1b = acc1[mt][nt][2 * p + 1], h3b = acc3[mt][nt][2 * p + 1];
                    float va = (h1a / (1.0f + __expf(-h1a))) * h3a;
                    float vb = (h1b / (1.0f + __expf(-h1b))) * h3b;
                    int n = n0 + wn * 32 + nt * 8 + tg * 2;
                    *(__half2*)&d_act[(size_t)(r0 + m) * I_DIM + n] =
                        __floats2half2_rn(va, vb);
                }
            }
        }
    }
}

// ---------------- GEMM2: d_y[slot] = gate * (act @ W2^T), fp16 MMA ----------------
// block tile 128(M) x 64(N); 8 warps 4m x 2n (warp 32x32); cp.async A; 2 CTAs/SM
// Plain float2 stores (no atomics); combine_kernel sums the two slots per token.
// grid: (H_DIM/64 = 16, MAX_TILES), block: 256
__global__ __launch_bounds__(256, 2)
void gemm2_kernel(const float* __restrict__ W2) {
    int tile = blockIdx.y;
    if (tile >= d_num_tiles) return;
    const int e    = d_tile_e[tile];
    const int r0   = d_tile_r0[tile];
    const int rows = d_tile_r1[tile] - r0;
    const int n0   = blockIdx.x * 64;

    __shared__ __half sA[2][128 * LDA];
    __shared__ __half sB[2][64 * LDA];

    const int tid  = threadIdx.x;
    const int warp = tid >> 5, lane = tid & 31;
    const int g = lane >> 2, tg = lane & 3;
    const int wm = warp & 3, wn = warp >> 2;     // warp tile (wm*32, wn*32)
    const int lrow = tid >> 3;                   // 0..31
    const int lk   = (tid & 7) * 4;
    const int q = lane >> 3, j = lane & 7;

    const int ar = tid >> 2;                     // 0..63 (+64)
    const int ac = (tid & 3) * 8;

    const __half* Ap  = d_act + (size_t)r0 * I_DIM;      // padded -> unconditional
    const float*  W2e = W2 + (size_t)e * H_DIM * I_DIM;

    float4 rB[2];

    // ---- stage 0 ----
#pragma unroll
    for (int i = 0; i < 2; i++) {
        int row = ar + 64 * i;
        CP_ASYNC_16(smem_u32(&sA[0][row * LDA + ac]), Ap + (size_t)row * I_DIM + ac);
    }
    CP_ASYNC_COMMIT();
#pragma unroll
    for (int i = 0; i < 2; i++)
        rB[i] = *(const float4*)(W2e + (size_t)(n0 + lrow + 32 * i) * I_DIM + lk);
#pragma unroll
    for (int i = 0; i < 2; i++) {
        uint2 u;
        u.x = pack2(rB[i].x, rB[i].y);
        u.y = pack2(rB[i].z, rB[i].w);
        *(uint2*)&sB[0][(lrow + 32 * i) * LDA + lk] = u;
    }
    CP_ASYNC_WAIT0();
    __syncthreads();

    float acc[2][4][4];
#pragma unroll
    for (int a = 0; a < 2; a++)
#pragma unroll
        for (int b = 0; b < 4; b++)
#pragma unroll
            for (int c = 0; c < 4; c++) acc[a][b][c] = 0.f;

    const int NT = I_DIM / BK;       // 88 K-tiles
    for (int t = 0; t < NT; t++) {
        const int cur = t & 1;
        const bool more = (t + 1 < NT);

        if (more) {
            const int kn = (t + 1) * BK;
            const int nxt = cur ^ 1;
#pragma unroll
            for (int i = 0; i < 2; i++) {
                int row = ar + 64 * i;
                CP_ASYNC_16(smem_u32(&sA[nxt][row * LDA + ac]),
                            Ap + (size_t)row * I_DIM + kn + ac);
            }
            CP_ASYNC_COMMIT();
#pragma unroll
            for (int i = 0; i < 2; i++)
                rB[i] = *(const float4*)(W2e + (size_t)(n0 + lrow + 32 * i) * I_DIM + kn + lk);
        }

#pragma unroll
        for (int ks = 0; ks < BK; ks += 16) {
            uint32_t af[2][4];
#pragma unroll
            for (int mt = 0; mt < 2; mt++) {
                int arow = wm * 32 + mt * 16 + j + (q & 1) * 8;
                int acol = ks + (q >> 1) * 8;
                ldsm_x4(af[mt], smem_u32(&sA[cur][arow * LDA + acol]));
            }
            uint32_t bf[2][4];
#pragma unroll
            for (int pr = 0; pr < 2; pr++) {
                int brow = wn * 32 + pr * 16 + j + (q >> 1) * 8;
                int bcol = ks + (q & 1) * 8;
                ldsm_x4(bf[pr], smem_u32(&sB[cur][brow * LDA + bcol]));
            }
#pragma unroll
            for (int mt = 0; mt < 2; mt++)
#pragma unroll
                for (int nt = 0; nt < 4; nt++) {
                    int pr = nt >> 1, o = (nt & 1) * 2;
                    mma_f16(acc[mt][nt], af[mt], bf[pr][o], bf[pr][o + 1]);
                }
        }

        if (more) {
            const int nxt = cur ^ 1;
#pragma unroll
            for (int i = 0; i < 2; i++) {
                uint2 u;
                u.x = pack2(rB[i].x, rB[i].y);
                u.y = pack2(rB[i].z, rB[i].w);
                *(uint2*)&sB[nxt][(lrow + 32 * i) * LDA + lk] = u;
            }
            CP_ASYNC_WAIT0();
            __syncthreads();
        }
    }

    // epilogue: d_y[slot] = gate * acc (plain stores, float2-vectorized)
    float gat_h[2][2];
    int   row_h[2][2];
#pragma unroll
    for (int mt = 0; mt < 2; mt++)
#pragma unroll
        for (int hh = 0; hh < 2; hh++) {
            int m = wm * 32 + mt * 16 + g + hh * 8;
            if (m < rows) {
                row_h[mt][hh] = r0 + m;
                gat_h[mt][hh] = d_slot_gate[r0 + m];
            } else {
                row_h[mt][hh] = -1;
                gat_h[mt][hh] = 0.f;
            }
        }

#pragma unroll
    for (int mt = 0; mt < 2; mt++) {
#pragma unroll
        for (int nt = 0; nt < 4; nt++) {
#pragma unroll
            for (int hh = 0; hh < 2; hh++) {
                int slot = row_h[mt][hh];
                if (slot >= 0) {
                    int n = n0 + wn * 32 + nt * 8 + tg * 2;
                    float2 v;
                    v.x = gat_h[mt][hh] * acc[mt][nt][2 * hh];
                    v.y = gat_h[mt][hh] * acc[mt][nt][2 * hh + 1];
                    *(float2*)(d_y + (size_t)slot * H_DIM + n) = v;
                }
            }
        }
    }
}

// ---------------- launch ----------------
extern "C" void kernel_launch(void* const* d_in, const int* in_sizes, int n_in,
                              void* d_out, int out_size) {
    const float* hs     = (const float*)d_in[0];   // [T, H]
    const float* logits = (const float*)d_in[1];   // [T, E]
    const float* w1     = (const float*)d_in[2];   // [E, I, H]
    const float* w3     = (const float*)d_in[3];   // [E, I, H]
    const float* w2     = (const float*)d_in[4];   // [E, H, I]
    float* out = (float*)d_out;                    // [T, H]

    router_kernel<<<1, T_TOK>>>(logits);
    gather_kernel<<<(S_NUM * H_DIM / 8) / 256, 256>>>(hs);
    gemm1_kernel<<<dim3(I_DIM / 64, MAX_TILES), 256>>>(w1, w3);
    gemm2_kernel<<<dim3(H_DIM / 64, MAX_TILES), 256>>>(w2);
    combine_kernel<<<(T_TOK * H_DIM / 4) / 256, 256>>>(out);
}